// round 5
// baseline (speedup 1.0000x reference)
#include <cuda_runtime.h>

typedef unsigned long long u64;
#define PI_F 3.14159265358979323846f
#define FULL 0xffffffffu

// ---------------------------------------------------------------------------
// State layout (per warp = one batch element, 1024 complex amps):
//   amp index i = (logical_lane << 5) | (k << 1) | c
//   qubits 0..4 -> logical lane bits 4..0, qubits 5..8 -> k bits 3..0,
//   qubit 9 -> f32x2 pack component.
// Lane CNOT-ring part (0,1)(1,2)(2,3)(3,4) = linear perm g(n)=n^(n>>1),
// handled as a relabel: thread tracks logical index p, gates use physical
// shfl masks g^L(K) (tables LM/M90).
// Layer 0 on |0..0> is built directly as a product state.
// Per-(batch,layer,qubit) fused SU(2) coefficients precomputed into g_F.
// ---------------------------------------------------------------------------

__device__ float4 g_W[40];                 // weight-only RZ*RY*RX per (layer,qubit)
__device__ float4 g_F[4096 * 40];          // fused RZ*RY*RX*RY(x) per (batch,layer,qubit)

__global__ void prep_w_kernel(const float* __restrict__ w) {
    int t = blockIdx.x * blockDim.x + threadIdx.x;
    if (t >= 40) return;
    float a = w[t * 3 + 0], b = w[t * 3 + 1], c = w[t * 3 + 2];
    float sa, ca, sb, cb, sc, cc;
    sincosf(0.5f * a, &sa, &ca);
    sincosf(0.5f * b, &sb, &cb);
    sincosf(0.5f * c, &sc, &cc);
    float m_ar = cb * ca, m_ai = sb * sa, m_br = -sb * ca, m_bi = -cb * sa;
    g_W[t] = make_float4(cc * m_ar + sc * m_ai,
                         cc * m_ai - sc * m_ar,
                         cc * m_br + sc * m_bi,
                         cc * m_bi - sc * m_br);
}

__global__ void fuse_kernel(const float* __restrict__ x) {
    int t = blockIdx.x * blockDim.x + threadIdx.x;
    if (t >= 4096 * 10) return;
    int b = t / 10, q = t - b * 10;
    float v = fminf(fmaxf(x[t], -PI_F), PI_F);
    float s, c;
    sincosf(0.5f * v, &s, &c);
#pragma unroll
    for (int l = 0; l < 4; ++l) {
        float4 w = g_W[l * 10 + q];
        g_F[b * 40 + l * 10 + q] = make_float4(
            w.x * c + w.z * s,
            w.y * c + w.w * s,
            w.z * c - w.x * s,
            w.w * c - w.y * s);
    }
}

// ---- f32x2 helpers ----
__device__ __forceinline__ u64 pk(float lo, float hi) {
    u64 r; asm("mov.b64 %0, {%1, %2};" : "=l"(r) : "f"(lo), "f"(hi)); return r;
}
__device__ __forceinline__ void unpk(u64 v, float& lo, float& hi) {
    asm("mov.b64 {%0, %1}, %2;" : "=f"(lo), "=f"(hi) : "l"(v));
}
__device__ __forceinline__ u64 dup2(float x) { return pk(x, x); }
__device__ __forceinline__ u64 f2fma(u64 a, u64 b, u64 c) {
    u64 d; asm("fma.rn.f32x2 %0, %1, %2, %3;" : "=l"(d) : "l"(a), "l"(b), "l"(c)); return d;
}
__device__ __forceinline__ u64 f2mul(u64 a, u64 b) {
    u64 d; asm("mul.rn.f32x2 %0, %1, %2;" : "=l"(d) : "l"(a), "l"(b)); return d;
}
__device__ __forceinline__ u64 f2add(u64 a, u64 b) {
    u64 d; asm("add.rn.f32x2 %0, %1, %2;" : "=l"(d) : "l"(a), "l"(b)); return d;
}
__device__ __forceinline__ u64 swap2(u64 v) {
    float a, b; unpk(v, a, b); return pk(b, a);
}
__device__ __forceinline__ u64 shflx2(u64 v, int m) {
    float a, b; unpk(v, a, b);
    a = __shfl_xor_sync(FULL, a, m);
    b = __shfl_xor_sync(FULL, b, m);
    return pk(a, b);
}

// inverse of g(n)=n^(n>>1) on 5 bits (prefix-xor)
__device__ __forceinline__ int ginv5(int n) {
    n ^= n >> 1; n ^= n >> 2; n ^= n >> 4;
    return n & 31;
}

// ---- SU(2) on a lane qubit: physical shfl mask KS, logical row-select hi ----
__device__ __forceinline__ void u_lane(u64 (&Xr)[16], u64 (&Xi)[16],
                                       float ar, float ai, float br, float bi,
                                       bool hi, int KS) {
    const float di = hi ? -ai : ai;
    const float orr = hi ? -br : br;
    const u64 ar2 = dup2(ar), di2 = dup2(di), ndi2 = dup2(-di);
    const u64 or2 = dup2(orr), bi2 = dup2(bi), nbi2 = dup2(-bi);
#pragma unroll
    for (int k = 0; k < 16; ++k) {
        u64 Pr = shflx2(Xr[k], KS);
        u64 Pi = shflx2(Xi[k], KS);
        u64 nr = f2fma(ar2, Xr[k], f2fma(ndi2, Xi[k], f2fma(or2, Pr, f2mul(nbi2, Pi))));
        u64 ni = f2fma(ar2, Xi[k], f2fma(di2, Xr[k], f2fma(or2, Pi, f2mul(bi2, Pr))));
        Xr[k] = nr; Xi[k] = ni;
    }
}

// ---- SU(2) on k-space bit MK (qubits 5..8) ----
template<int MK>
__device__ __forceinline__ void u_localk(u64 (&Xr)[16], u64 (&Xi)[16],
                                         float ar, float ai, float br, float bi) {
    const u64 ar2 = dup2(ar), ai2 = dup2(ai), br2 = dup2(br), bi2 = dup2(bi);
    const u64 nai2 = dup2(-ai), nbr2 = dup2(-br), nbi2 = dup2(-bi);
#pragma unroll
    for (int k = 0; k < 16; ++k) if (!(k & MK)) {
        const int h = k | MK;
        u64 Ar = Xr[k], Ai = Xi[k], Br = Xr[h], Bi = Xi[h];
        Xr[k] = f2fma(ar2,  Ar, f2fma(nai2, Ai, f2fma(br2,  Br, f2mul(nbi2, Bi))));
        Xi[k] = f2fma(ai2,  Ar, f2fma(ar2,  Ai, f2fma(bi2,  Br, f2mul(br2,  Bi))));
        Xr[h] = f2fma(nbr2, Ar, f2fma(nbi2, Ai, f2fma(ar2,  Br, f2mul(ai2,  Bi))));
        Xi[h] = f2fma(bi2,  Ar, f2fma(nbr2, Ai, f2fma(nai2, Br, f2mul(ar2,  Bi))));
    }
}

// ---- SU(2) on qubit 9 (within-pack component) ----
__device__ __forceinline__ void u_q9(u64 (&Xr)[16], u64 (&Xi)[16],
                                     float ar, float ai, float br, float bi) {
    const u64 ar2 = dup2(ar);
    const u64 brm = pk(br, -br);
    const u64 aim = pk(-ai, ai);
    const u64 aim2 = pk(ai, -ai);
    const u64 bin = dup2(-bi);
    const u64 bi2 = dup2(bi);
#pragma unroll
    for (int k = 0; k < 16; ++k) {
        u64 sR = swap2(Xr[k]);
        u64 sI = swap2(Xi[k]);
        u64 nr = f2fma(ar2, Xr[k], f2fma(brm, sR, f2fma(aim,  Xi[k], f2mul(bin, sI))));
        u64 ni = f2fma(ar2, Xi[k], f2fma(brm, sI, f2fma(aim2, Xr[k], f2mul(bi2, sR))));
        Xr[k] = nr; Xi[k] = ni;
    }
}

template<int CM, int TM>
__device__ __forceinline__ void cnot_kk(u64 (&Xr)[16], u64 (&Xi)[16]) {
#pragma unroll
    for (int k = 0; k < 16; ++k) if ((k & CM) && !(k & TM)) {
        const int h = k | TM;
        u64 t = Xr[k]; Xr[k] = Xr[h]; Xr[h] = t;
        t = Xi[k]; Xi[k] = Xi[h]; Xi[h] = t;
    }
}

// CNOT ring tail: (4,5) cond swap, k renames, (8,9), (9,0) with physical mask
__device__ __forceinline__ void ring_tail(u64 (&Xr)[16], u64 (&Xi)[16],
                                          bool c45, int m90) {
    if (c45) {
#pragma unroll
        for (int k = 0; k < 8; ++k) {
            const int h = k | 8;
            u64 t = Xr[k]; Xr[k] = Xr[h]; Xr[h] = t;
            t = Xi[k]; Xi[k] = Xi[h]; Xi[h] = t;
        }
    }
    cnot_kk<8, 4>(Xr, Xi);
    cnot_kk<4, 2>(Xr, Xi);
    cnot_kk<2, 1>(Xr, Xi);
#pragma unroll
    for (int k = 1; k < 16; k += 2) {
        Xr[k] = swap2(Xr[k]);
        Xi[k] = swap2(Xi[k]);
    }
#pragma unroll
    for (int k = 0; k < 16; ++k) {
        float l0, h0;
        unpk(Xr[k], l0, h0);
        h0 = __shfl_xor_sync(FULL, h0, m90);
        Xr[k] = pk(l0, h0);
        unpk(Xi[k], l0, h0);
        h0 = __shfl_xor_sync(FULL, h0, m90);
        Xi[k] = pk(l0, h0);
    }
}

__global__ void __launch_bounds__(128, 5)
qsim_kernel(float* __restrict__ out)
{
    __shared__ float4 sF[4][40];
    const unsigned lane = threadIdx.x & 31u;
    const int wib = threadIdx.x >> 5;
    const int warp = blockIdx.x * 4 + wib;

    // warp-cooperative copy of this batch element's 40 fused gate quadruples
    {
        const float4* src = g_F + warp * 40;
        for (int i = lane; i < 40; i += 32) sF[wib][i] = src[i];
        __syncwarp();
    }
    const float4* __restrict__ sFw = sF[wib];

    u64 Xr[16], Xi[16];

    // ======== layer 0: direct product-state construction ========
    // U_q|0> = (alpha, -conj(beta)) = ((ar,ai), (-br, bi))
    {
        // lane factor over qubits 0..4 (identity labeling at layer 0)
        float Fr, Fi;
        {
            float4 f = sFw[0];
            bool b = (lane & 16) != 0;
            Fr = b ? -f.z : f.x;
            Fi = b ?  f.w : f.y;
        }
#pragma unroll
        for (int q = 1; q < 5; ++q) {
            float4 f = sFw[q];
            bool b = (lane & (16u >> q)) != 0;
            float er = b ? -f.z : f.x, ei = b ? f.w : f.y;
            float nr = Fr * er - Fi * ei;
            float ni = Fr * ei + Fi * er;
            Fr = nr; Fi = ni;
        }
        // fold qubit 9 (pack component) into F
        float4 f9 = sFw[9];
        u64 B0r = pk(f9.x, -f9.z);
        u64 B0i = pk(f9.y,  f9.w);
        u64 Fr2 = dup2(Fr), Fi2 = dup2(Fi), nFi2 = dup2(-Fi);
        u64 FBr = f2fma(Fr2, B0r, f2mul(nFi2, B0i));
        u64 FBi = f2fma(Fr2, B0i, f2mul(Fi2, B0r));
        // product over q5 (k bit3), q6 (bit2), q7 (bit1), q8 (bit0)
        float4 f5 = sFw[5], f6 = sFw[6], f7 = sFw[7], f8 = sFw[8];
        float c2r[2] = {f5.x, -f5.z}, c2i[2] = {f5.y, f5.w};
        float c4r[4], c4i[4];
#pragma unroll
        for (int j = 0; j < 4; ++j) {
            float er = (j & 1) ? -f6.z : f6.x, ei = (j & 1) ? f6.w : f6.y;
            int h = j >> 1;
            c4r[j] = c2r[h] * er - c2i[h] * ei;
            c4i[j] = c2r[h] * ei + c2i[h] * er;
        }
#pragma unroll
        for (int h = 0; h < 8; ++h) {
            float er = (h & 1) ? -f7.z : f7.x, ei = (h & 1) ? f7.w : f7.y;
            int j = h >> 1;
            float c8r = c4r[j] * er - c4i[j] * ei;
            float c8i = c4r[j] * ei + c4i[j] * er;
#pragma unroll
            for (int c = 0; c < 2; ++c) {
                float gr = c ? -f8.z : f8.x, gi = c ? f8.w : f8.y;
                float mr = c8r * gr - c8i * gi;
                float mi = c8r * gi + c8i * gr;
                u64 mr2 = dup2(mr), mi2 = dup2(mi), nmi2 = dup2(-mi);
                const int k = 2 * h + c;
                Xr[k] = f2fma(mr2, FBr, f2mul(nmi2, FBi));
                Xi[k] = f2fma(mr2, FBi, f2mul(mi2, FBr));
            }
        }
    }

    // layer-0 CNOT ring: lane part is a relabel; tail applied physically
    int p = ginv5((int)lane);                 // logical index of this thread
    ring_tail(Xr, Xi, (p & 1) != 0, 24);      // m90 = g^1(16) = 24

    // physical shfl masks g^L(K) for logical K = 16>>q, and g^{L+1}(16)
    const int LM[4][5] = {{16,8,4,2,1},{24,12,6,3,1},{20,10,5,2,1},{30,15,7,3,1}};
    const int M90[4] = {24, 20, 30, 17};

    // ======== layers 1..3 ========
#pragma unroll
    for (int L = 1; L < 4; ++L) {
#define GATEC(Q)                                                   \
            float4 wc = sFw[L * 10 + (Q)];                         \
            float ar = wc.x, ai = wc.y, br = wc.z, bi = wc.w;
        { GATEC(0) u_lane(Xr, Xi, ar, ai, br, bi, (p & 16) != 0, LM[L][0]); }
        { GATEC(1) u_lane(Xr, Xi, ar, ai, br, bi, (p &  8) != 0, LM[L][1]); }
        { GATEC(2) u_lane(Xr, Xi, ar, ai, br, bi, (p &  4) != 0, LM[L][2]); }
        { GATEC(3) u_lane(Xr, Xi, ar, ai, br, bi, (p &  2) != 0, LM[L][3]); }
        { GATEC(4) u_lane(Xr, Xi, ar, ai, br, bi, (p &  1) != 0, LM[L][4]); }
        { GATEC(5) u_localk<8>(Xr, Xi, ar, ai, br, bi); }
        { GATEC(6) u_localk<4>(Xr, Xi, ar, ai, br, bi); }
        { GATEC(7) u_localk<2>(Xr, Xi, ar, ai, br, bi); }
        { GATEC(8) u_localk<1>(Xr, Xi, ar, ai, br, bi); }
        { GATEC(9) u_q9(Xr, Xi, ar, ai, br, bi); }
#undef GATEC
        p = ginv5(p);                          // lane ring as relabel
        ring_tail(Xr, Xi, (p & 1) != 0, M90[L]);
    }

    // ======== measurement: <Z_q> ========
    u64 tot2 = 0ull, s5 = 0ull, s6 = 0ull, s7 = 0ull, s8 = 0ull;
    const u64 N1 = dup2(-1.0f);
#pragma unroll
    for (int k = 0; k < 16; ++k) {
        u64 P = f2fma(Xr[k], Xr[k], f2mul(Xi[k], Xi[k]));
        tot2 = f2add(tot2, P);
        s5 = (k & 8) ? f2fma(P, N1, s5) : f2add(s5, P);
        s6 = (k & 4) ? f2fma(P, N1, s6) : f2add(s6, P);
        s7 = (k & 2) ? f2fma(P, N1, s7) : f2add(s7, P);
        s8 = (k & 1) ? f2fma(P, N1, s8) : f2add(s8, P);
    }
    float tl, th;
    unpk(tot2, tl, th);
    const float tot = tl + th;
    float z[10];
    z[0] = (p & 16) ? -tot : tot;
    z[1] = (p &  8) ? -tot : tot;
    z[2] = (p &  4) ? -tot : tot;
    z[3] = (p &  2) ? -tot : tot;
    z[4] = (p &  1) ? -tot : tot;
    { float a, b; unpk(s5, a, b); z[5] = a + b; }
    { float a, b; unpk(s6, a, b); z[6] = a + b; }
    { float a, b; unpk(s7, a, b); z[7] = a + b; }
    { float a, b; unpk(s8, a, b); z[8] = a + b; }
    z[9] = tl - th;

#pragma unroll
    for (int q = 0; q < 10; ++q) {
#pragma unroll
        for (int k = 16; k >= 1; k >>= 1)
            z[q] += __shfl_xor_sync(FULL, z[q], k);
    }
    if (lane == 0) {
#pragma unroll
        for (int q = 0; q < 10; ++q)
            out[warp * 10 + q] = z[q];
    }
}

extern "C" void kernel_launch(void* const* d_in, const int* in_sizes, int n_in,
                              void* d_out, int out_size) {
    const float* a = (const float*)d_in[0];
    const float* b = (const float*)d_in[1];
    const float* x = a;
    const float* w = b;
    if (n_in >= 2 && in_sizes[0] == 120 && in_sizes[1] == 40960) { x = b; w = a; }
    float* out = (float*)d_out;
    prep_w_kernel<<<1, 64>>>(w);
    fuse_kernel<<<(4096 * 10 + 127) / 128, 128>>>(x);
    qsim_kernel<<<1024, 128>>>(out);
}